// round 16
// baseline (speedup 1.0000x reference)
#include <cuda_runtime.h>
#include <cuda_fp16.h>
#include <math.h>

typedef unsigned int u32;

#define NCH 32
#define GRID 152
#define HSTRB 528        // H row stride bytes (256 fp16 + pad) ; 528/16=33 odd -> LDSM conflict-free
#define DSTRB 1056       // DS row stride bytes (264 f32)
#define WHSTB 68         // WH row stride bytes (34 halves, 17 words: conflict-free)

#define H_OFF   0                       // 128*528   = 67584
#define DS_OFF  67584                   // 128*1056  = 135168
#define WH_OFF  202752                  // 256*68    = 17408
#define PAR     220160
#define MC_OFF  (PAR)                   // 32*12 f32
#define MA_OFF  (PAR + 1536)            // 5*12 f32
#define NSC_OFF (PAR + 1792)
#define LB_OFF  (PAR + 1920)
#define RW_OFF  (PAR + 2048)
#define RB_OFF  (PAR + 2176)
#define SMEM_TOTAL (PAR + 2192)         // 222352 B

__device__ __forceinline__ u32 smem_u32(const void* p) {
    u32 a; asm("{ .reg .u64 t; cvta.to.shared.u64 t, %1; cvt.u32.u64 %0, t; }" : "=r"(a) : "l"(p));
    return a;
}
#define LDSM_X4(r, a) \
    asm volatile("ldmatrix.sync.aligned.m8n8.x4.shared.b16 {%0,%1,%2,%3}, [%4];" \
        : "=r"((r)[0]), "=r"((r)[1]), "=r"((r)[2]), "=r"((r)[3]) : "r"(a))
#define HMMA(d, a, B0, B1) \
    asm volatile("mma.sync.aligned.m16n8k16.row.col.f32.f16.f16.f32 " \
        "{%0,%1,%2,%3}, {%4,%5,%6,%7}, {%8,%9}, {%0,%1,%2,%3};" \
        : "+f"((d)[0]), "+f"((d)[1]), "+f"((d)[2]), "+f"((d)[3]) \
        : "r"((a)[0]), "r"((a)[1]), "r"((a)[2]), "r"((a)[3]), "r"(B0), "r"(B1))

__device__ __forceinline__ void rotor_exp4(float b0, float b1, float b2, float r[4]) {
    float t2 = fmaf(b0, b0, fmaf(b1, b1, b2 * b2));
    float th = sqrtf(t2), sn, cs;
    sincosf(th, &sn, &cs);
    float sinc = (th > 1e-6f) ? sn / fmaxf(th, 1e-6f) : 1.0f;
    r[0] = cs; r[1] = sinc * b0; r[2] = sinc * b1; r[3] = sinc * b2;
}
__device__ __forceinline__ void rotor_to_mat(const float u[4], float m[9]) {
    const float qw = u[0], qx = -u[3], qy = u[2], qz = -u[1];
    const float x2 = qx + qx, y2 = qy + qy, z2 = qz + qz;
    const float xx = qx * x2, yy = qy * y2, zz = qz * z2;
    const float xy = qx * y2, xz = qx * z2, yz = qy * z2;
    const float wx = qw * x2, wy = qw * y2, wz = qw * z2;
    m[0] = 1.f - (yy + zz); m[1] = xy - wz;        m[2] = xz + wy;
    m[3] = xy + wz;         m[4] = 1.f - (xx + zz); m[5] = yz - wx;
    m[6] = xz - wy;         m[7] = yz + wx;        m[8] = 1.f - (xx + yy);
}
__device__ __forceinline__ void mat_apply(const float4 A0, const float4 A1, const float A2,
                                          float v1, float v2, float v3,
                                          float& o1, float& o2, float& o3) {
    o1 = fmaf(A0.x, v1, fmaf(A0.y, v2, A0.z * v3));
    o2 = fmaf(A0.w, v1, fmaf(A1.x, v2, A1.y * v3));
    o3 = fmaf(A1.z, v1, fmaf(A1.w, v2, A2  * v3));
}
__device__ __forceinline__ void sandwich(const float4 A0, const float4 A1, const float A2,
                                         const float4 vA, const float4 vB, float x[8]) {
    float xv1, xv2, xv3, xb1, xb2, xb3;
    mat_apply(A0, A1, A2, vA.y, vA.z, vB.x, xv1, xv2, xv3);
    mat_apply(A0, A1, A2, vB.z, -vB.y, vA.w, xb1, xb2, xb3);
    x[0] = vA.x; x[1] = xv1; x[2] = xv2; x[3] = xb3;
    x[4] = xv3;  x[5] = -xb2; x[6] = xb1; x[7] = vB.w;
}

__global__ __launch_bounds__(512, 1) void dynamics_kernel(
    const float* __restrict__ state, const int* __restrict__ action,
    const float* __restrict__ act_bv, const float* __restrict__ norm_scale,
    const float* __restrict__ rotor_bv, const float* __restrict__ lin_W,
    const float* __restrict__ lin_b, const float* __restrict__ reward_W,
    const float* __restrict__ reward_b, float* __restrict__ out, int B, int ntiles)
{
    extern __shared__ __align__(1024) unsigned char smem[];
    const u32 sb = smem_u32(smem);
    float* MC  = (float*)(smem + MC_OFF);
    float* MAm = (float*)(smem + MA_OFF);
    float* NSC = (float*)(smem + NSC_OFF);
    float* LBs = (float*)(smem + LB_OFF);
    float* RWs = (float*)(smem + RW_OFF);
    float* RBs = (float*)(smem + RB_OFF);

    const int tid = threadIdx.x, wid = tid >> 5, lane = tid & 31;

    // ---- stage once per persistent CTA ----
    // WH[n][i] fp16 = lin_W[n>>3][i][popc(n&7)], row stride 68B
    for (int v = tid; v < 256 * 32; v += 512) {
        const int n = v >> 5, i = v & 31;
        const float w = lin_W[(n >> 3) * 128 + i * 4 + __popc(n & 7)];
        *(__half*)(smem + WH_OFF + n * WHSTB + i * 2) = __float2half(w);
    }
    if (tid < NCH) {
        NSC[tid] = norm_scale[tid]; LBs[tid] = lin_b[tid]; RWs[tid] = reward_W[tid];
        float r[4], m[9];
        rotor_exp4(-0.5f * rotor_bv[tid * 3 + 0], -0.5f * rotor_bv[tid * 3 + 1],
                   -0.5f * rotor_bv[tid * 3 + 2], r);
        rotor_to_mat(r, m);
#pragma unroll
        for (int e = 0; e < 9; e++) MC[tid * 12 + e] = m[e];
    }
    if (tid >= 32 && tid < 37) {
        const int a = tid - 32;
        float r[4], m[9];
        rotor_exp4(-0.5f * act_bv[a * 3 + 0], -0.5f * act_bv[a * 3 + 1],
                   -0.5f * act_bv[a * 3 + 2], r);
        rotor_to_mat(r, m);
#pragma unroll
        for (int e = 0; e < 9; e++) MAm[a * 12 + e] = m[e];
    }
    if (tid == 40) RBs[0] = reward_b[0];
    __syncthreads();

    // hoisted per-lane channel params (phases A and C use c = lane)
    const int c = lane;
    const float4 C0 = *(const float4*)&MC[c * 12 + 0];
    const float4 C1 = *(const float4*)&MC[c * 12 + 4];
    const float  C2 = MC[c * 12 + 8];
    const float nsc = NSC[c], lb_c = LBs[c], rw_c = RWs[c], rb = RBs[0];

    // mma decomposition: warp = (M-half, 32-col slab)
    const int m0w = (wid & 1) * 64, n0w = (wid >> 1) * 32;
    const int g = lane >> 2, cc4 = lane & 3;
    const bool cbit = ((g >> 1) == cc4);
    const bool even = ((g & 1) == 0);
    const u32 aAddrBase = sb + H_OFF + (u32)(m0w + (lane & 15)) * HSTRB + (u32)(lane >> 4) * 16;

    for (int tile = blockIdx.x; tile < ntiles; tile += GRID) {

        // ======== Phase A: prework -> H fp16 [row=b_local][k=c*8+dd] ========
#pragma unroll 2
        for (int q = 0; q < 8; q++) {
            const int bl = 16 * q + wid;
            const int bg = tile * 128 + bl;
            const int bc = (bg < B) ? bg : (B - 1);
            const int act = action[bc];
            const float4 A0 = *(const float4*)&MAm[act * 12 + 0];
            const float4 A1 = *(const float4*)&MAm[act * 12 + 4];
            const float  A2 = MAm[act * 12 + 8];
            const float4* sp = (const float4*)(state + ((size_t)bc * NCH + c) * 8);
            const float4 vA = sp[0], vB = sp[1];

            float x[8];
            sandwich(A0, A1, A2, vA, vB, x);
            float nn = 1e-6f;
#pragma unroll
            for (int d = 0; d < 8; d++) nn = fmaf(x[d], x[d], nn);
            const float inv = rsqrtf(nn) * nsc;
            const float gate = 0.5f * (1.0f + erff(x[0] * inv * 0.70710678118654752f));
            const float sc = inv * gate;
            float h[8];
#pragma unroll
            for (int d = 0; d < 8; d++) h[d] = x[d] * sc;

            float yv1, yv2, yv3, yb1, yb2, yb3;
            mat_apply(C0, C1, C2, h[1], h[2], h[4], yv1, yv2, yv3);
            mat_apply(C0, C1, C2, h[6], -h[5], h[3], yb1, yb2, yb3);

            __half2 p0 = __floats2half2_rn(h[0], yv1);
            __half2 p1 = __floats2half2_rn(yv2, yb3);
            __half2 p2 = __floats2half2_rn(yv3, -yb2);
            __half2 p3 = __floats2half2_rn(yb1, h[7]);
            uint4 qv;
            qv.x = *(u32*)&p0; qv.y = *(u32*)&p1; qv.z = *(u32*)&p2; qv.w = *(u32*)&p3;
            *(uint4*)(smem + H_OFF + bl * HSTRB + c * 16) = qv;
        }
        __syncthreads();

        // ======== Phase B: HMMA D = H * WBK (block-diag, B frags analytic) ========
        {
            float acc[64];   // [mt][t][4]
#pragma unroll
            for (int e = 0; e < 64; e++) acc[e] = 0.f;

#pragma unroll 2
            for (int s = 0; s < 16; s++) {
                u32 b0[4], b1[4];
#pragma unroll
                for (int t = 0; t < 4; t++) {
                    u32 w2 = *(const u32*)(smem + WH_OFF + (n0w + 8 * t + g) * WHSTB + 4 * s);
                    w2 = cbit ? w2 : 0u;
                    b0[t] = even ? (w2 & 0xFFFFu) : (w2 << 16);
                    b1[t] = even ? (w2 >> 16) : (w2 & 0xFFFF0000u);
                }
#pragma unroll
                for (int mt = 0; mt < 4; mt++) {
                    u32 af[4];
                    LDSM_X4(af, aAddrBase + (u32)(16 * mt) * HSTRB + 32u * s);
#pragma unroll
                    for (int t = 0; t < 4; t++)
                        HMMA(&acc[(mt * 4 + t) * 4], af, b0[t], b1[t]);
                }
            }
            // store D f32 to DS
#pragma unroll
            for (int mt = 0; mt < 4; mt++) {
#pragma unroll
                for (int t = 0; t < 4; t++) {
                    const int r0 = m0w + 16 * mt + g;
                    const int n = n0w + 8 * t + 2 * cc4;
                    float2 lo; lo.x = acc[(mt * 4 + t) * 4 + 0]; lo.y = acc[(mt * 4 + t) * 4 + 1];
                    float2 hi; hi.x = acc[(mt * 4 + t) * 4 + 2]; hi.y = acc[(mt * 4 + t) * 4 + 3];
                    *(float2*)(smem + DS_OFF + r0 * DSTRB + n * 4) = lo;
                    *(float2*)(smem + DS_OFF + (r0 + 8) * DSTRB + n * 4) = hi;
                }
            }
        }
        __syncthreads();

        // ======== Phase C: residual recompute + combine + store + reward ========
#pragma unroll 2
        for (int q = 0; q < 8; q++) {
            const int bl = 16 * q + wid;
            const int bg = tile * 128 + bl;
            const int bc = (bg < B) ? bg : (B - 1);
            const int act = action[bc];
            const float4 A0 = *(const float4*)&MAm[act * 12 + 0];
            const float4 A1 = *(const float4*)&MAm[act * 12 + 4];
            const float  A2 = MAm[act * 12 + 8];
            const float4* sp = (const float4*)(state + ((size_t)bc * NCH + c) * 8);
            const float4 vA = sp[0], vB = sp[1];
            float x[8];
            sandwich(A0, A1, A2, vA, vB, x);

            const float4 d0 = *(const float4*)(smem + DS_OFF + bl * DSTRB + c * 32);
            const float4 d1 = *(const float4*)(smem + DS_OFF + bl * DSTRB + c * 32 + 16);
            float f[8];
            f[0] = d0.x + x[0] + lb_c; f[1] = d0.y + x[1];
            f[2] = d0.z + x[2];        f[3] = d0.w + x[3];
            f[4] = d1.x + x[4];        f[5] = d1.y + x[5];
            f[6] = d1.z + x[6];        f[7] = d1.w + x[7];

            if (bg < B) {
                float4* op = (float4*)(out + B + (size_t)bg * 256 + c * 8);
                op[0] = make_float4(f[0], f[1], f[2], f[3]);
                op[1] = make_float4(f[4], f[5], f[6], f[7]);
            }
            float rv = f[0] * rw_c;
#pragma unroll
            for (int off = 16; off; off >>= 1) rv += __shfl_xor_sync(0xffffffffu, rv, off);
            if (lane == 0 && bg < B) out[bg] = rv + rb;
        }
        __syncthreads();   // protect H/DS before next tile overwrites
    }
}

extern "C" void kernel_launch(void* const* d_in, const int* in_sizes, int n_in,
                              void* d_out, int out_size) {
    const float* state      = (const float*)d_in[0];
    const int*   action     = (const int*)  d_in[1];
    const float* act_bv     = (const float*)d_in[2];
    const float* norm_scale = (const float*)d_in[3];
    const float* rotor_bv   = (const float*)d_in[4];
    const float* lin_W      = (const float*)d_in[5];
    const float* lin_b      = (const float*)d_in[6];
    const float* reward_W   = (const float*)d_in[7];
    const float* reward_b   = (const float*)d_in[8];
    float* out = (float*)d_out;
    const int B = in_sizes[1];
    const int ntiles = (B + 127) / 128;
    const int blocks = (ntiles < GRID) ? ntiles : GRID;

    cudaFuncSetAttribute(dynamics_kernel,
                         cudaFuncAttributeMaxDynamicSharedMemorySize, SMEM_TOTAL);
    dynamics_kernel<<<blocks, 512, SMEM_TOTAL>>>(state, action, act_bv, norm_scale,
                                                 rotor_bv, lin_W, lin_b, reward_W,
                                                 reward_b, out, B, ntiles);
}